// round 1
// baseline (speedup 1.0000x reference)
#include <cuda_runtime.h>

// Scratch (device globals — no dynamic allocation allowed)
__device__ float g_p0[8 * 64 * 2 * 64 * 64];   // pooled input  (n,t,c,64,64)  16 MB
__device__ float g_p1[8 * 64 * 4 * 16 * 16];   // pooled spikes1 (n,t,c,16,16)  2 MB
__device__ float g_p2[8 * 64 * 128];           // features       (n,t,128)    256 KB

// ---------------------------------------------------------------------------
// K1: avgpool4 over (y,x) of inp (n=8, c=2, 256, 256, t=64)  ->  g_p0 (n,t,c,64,64)
// Block = (Y, c, n); 256 threads. Reads t-contiguous (coalesced 128B), writes
// via padded-smem transpose so each t-row of 64 floats is contiguous.
// ---------------------------------------------------------------------------
__global__ __launch_bounds__(256) void k_pool(const float* __restrict__ inp) {
    int Y = blockIdx.x, c = blockIdx.y, n = blockIdx.z;
    __shared__ float sm[64 * 65];
    int tid = threadIdx.x;
    int t = tid & 63, Xi = tid >> 6;
    const float* base = inp + (((n * 2 + c) * 256 + 4 * Y) * 256) * 64;
#pragma unroll
    for (int it = 0; it < 16; ++it) {
        int X = Xi + it * 4;
        float acc = 0.f;
#pragma unroll
        for (int dy = 0; dy < 4; ++dy)
#pragma unroll
            for (int dx = 0; dx < 4; ++dx)
                acc += base[(dy * 256 + 4 * X + dx) * 64 + t];
        sm[X * 65 + t] = acc * 0.0625f;
    }
    __syncthreads();
    float* ob = g_p0 + n * 524288 + c * 4096 + Y * 64;   // + t*8192 later
#pragma unroll
    for (int it = 0; it < 16; ++it) {
        int idx = it * 256 + tid;
        int tw = idx >> 6, Xw = idx & 63;
        ob[tw * 8192 + Xw] = sm[Xw * 65 + tw];
    }
}

// ---------------------------------------------------------------------------
// K2: conv7 (2->4ch, pad 3) on 64x64 + IAF over t + avgpool4 -> g_p1
// Block = (ytile 0..15, n 0..7); 256 threads = 4 rows x 64 cols.
// Each thread: one pixel, all 4 c_out, IAF states in registers, t-serial.
// ---------------------------------------------------------------------------
__global__ __launch_bounds__(256) void k_conv1(const float* __restrict__ w0) {
    int tile = blockIdx.x, n = blockIdx.y;
    int tid = threadIdx.x;
    int y = tid >> 6, x = tid & 63;

    __shared__ float  si[1400];          // [cin 2][row 10][col 70]
    __shared__ float4 sw[98];            // [cin*49 + k] -> weights for 4 couts
    __shared__ float  spr[4][16][4];     // [y][gx][cout] pool partials

    if (tid < 98) {
        int cin = tid / 49, k = tid - cin * 49;
        sw[cin * 49 + k] = make_float4(w0[cin * 49 + k],       w0[(2 + cin) * 49 + k],
                                       w0[(4 + cin) * 49 + k], w0[(6 + cin) * 49 + k]);
    }

    float v0 = 0.f, v1 = 0.f, v2 = 0.f, v3 = 0.f;   // IAF membrane state
    int Y0 = tile * 4;
    const float* pb = g_p0 + n * 524288;
    float* ob = g_p1 + n * 65536 + tile * 16;
    const unsigned m = 0xffffffffu;

    for (int t = 0; t < 64; ++t) {
        __syncthreads();
        const float* pt = pb + t * 8192;
        for (int e = tid; e < 1400; e += 256) {
            int cin = e / 700, rem = e - cin * 700;
            int r = rem / 70, col = rem - r * 70;
            int gy = Y0 - 3 + r, gx = col - 3;
            float val = 0.f;
            if ((unsigned)gy < 64u && (unsigned)gx < 64u)
                val = pt[cin * 4096 + gy * 64 + gx];
            si[e] = val;
        }
        __syncthreads();

        float a0 = 0.f, a1 = 0.f, a2 = 0.f, a3 = 0.f;
#pragma unroll
        for (int cin = 0; cin < 2; ++cin)
#pragma unroll
            for (int dy = 0; dy < 7; ++dy)
#pragma unroll
                for (int dx = 0; dx < 7; ++dx) {
                    float vin = si[cin * 700 + (y + dy) * 70 + (x + dx)];
                    float4 w = sw[cin * 49 + dy * 7 + dx];
                    a0 += vin * w.x; a1 += vin * w.y;
                    a2 += vin * w.z; a3 += vin * w.w;
                }

        v0 += a0; v1 += a1; v2 += a2; v3 += a3;
        float s0 = (v0 >= 1.f) ? 1.f : 0.f; v0 -= s0;
        float s1 = (v1 >= 1.f) ? 1.f : 0.f; v1 -= s1;
        float s2 = (v2 >= 1.f) ? 1.f : 0.f; v2 -= s2;
        float s3 = (v3 >= 1.f) ? 1.f : 0.f; v3 -= s3;

        // pool 4x4: reduce groups of 4 x-lanes within warp, then 4 y-rows via smem
        s0 += __shfl_down_sync(m, s0, 2); s0 += __shfl_down_sync(m, s0, 1);
        s1 += __shfl_down_sync(m, s1, 2); s1 += __shfl_down_sync(m, s1, 1);
        s2 += __shfl_down_sync(m, s2, 2); s2 += __shfl_down_sync(m, s2, 1);
        s3 += __shfl_down_sync(m, s3, 2); s3 += __shfl_down_sync(m, s3, 1);
        if ((x & 3) == 0) {
            int gx = x >> 2;
            spr[y][gx][0] = s0; spr[y][gx][1] = s1;
            spr[y][gx][2] = s2; spr[y][gx][3] = s3;
        }
        __syncthreads();
        if (tid < 64) {
            int c = tid >> 4, gx = tid & 15;
            float sum = spr[0][gx][c] + spr[1][gx][c] + spr[2][gx][c] + spr[3][gx][c];
            ob[t * 1024 + c * 256 + gx] = sum * 0.0625f;
        }
    }
}

// ---------------------------------------------------------------------------
// K3: conv7 (4->8ch, pad 3) on 16x16 + IAF + avgpool4 -> g_p2 features (n,t,128)
// Block = (ytile 0..3, cout 0..7, n 0..7); 64 threads = 4 rows x 16 cols.
// One cout per thread; 4 partial accumulators to break the FFMA dep chain.
// ---------------------------------------------------------------------------
__global__ __launch_bounds__(64) void k_conv2(const float* __restrict__ w1) {
    int tile = blockIdx.x, co = blockIdx.y, n = blockIdx.z;
    int tid = threadIdx.x;
    int y = tid >> 4, x = tid & 15;

    __shared__ float si[880];     // [cin 4][row 10][col 22]
    __shared__ float sw[196];
    __shared__ float spr[2][4];

    for (int e = tid; e < 196; e += 64) sw[e] = w1[co * 196 + e];

    float vmem = 0.f;
    int Y0 = tile * 4;
    const float* pb = g_p1 + n * 65536;
    float* ob = g_p2 + n * 8192;
    const unsigned m = 0xffffffffu;

    for (int t = 0; t < 64; ++t) {
        __syncthreads();
        const float* pt = pb + t * 1024;
        for (int e = tid; e < 880; e += 64) {
            int cin = e / 220, rem = e - cin * 220;
            int r = rem / 22, col = rem - r * 22;
            int gy = Y0 - 3 + r, gx = col - 3;
            float val = 0.f;
            if ((unsigned)gy < 16u && (unsigned)gx < 16u)
                val = pt[cin * 256 + gy * 16 + gx];
            si[e] = val;
        }
        __syncthreads();

        float a[4] = {0.f, 0.f, 0.f, 0.f};
#pragma unroll
        for (int cin = 0; cin < 4; ++cin)
#pragma unroll
            for (int dy = 0; dy < 7; ++dy)
#pragma unroll
                for (int dx = 0; dx < 7; ++dx) {
                    float vin = si[cin * 220 + (y + dy) * 22 + (x + dx)];
                    a[dx & 3] += vin * sw[cin * 49 + dy * 7 + dx];
                }

        vmem += (a[0] + a[1]) + (a[2] + a[3]);
        float s = (vmem >= 1.f) ? 1.f : 0.f; vmem -= s;

        // pool 4x4: warp covers 2 rows x 16 cols
        s += __shfl_down_sync(m, s, 16);   // add row y+1
        s += __shfl_down_sync(m, s, 2);
        s += __shfl_down_sync(m, s, 1);
        if ((tid & 31) < 16 && (x & 3) == 0) spr[tid >> 5][x >> 2] = s;
        __syncthreads();
        if (tid < 4) {
            float sum = spr[0][tid] + spr[1][tid];
            ob[t * 128 + co * 16 + tile * 4 + tid] = sum * 0.0625f;
        }
    }
}

// ---------------------------------------------------------------------------
// K4: out[n][cls][t] = sum_f feat[n][t][f] * wl[cls][f]   (8,2,64)
// ---------------------------------------------------------------------------
__global__ __launch_bounds__(128) void k_fc(const float* __restrict__ wl,
                                            float* __restrict__ out) {
    int b = blockIdx.x;          // n*64 + t
    int tid = threadIdx.x;
    float v = g_p2[b * 128 + tid];
    float c0 = v * wl[tid];
    float c1 = v * wl[128 + tid];
    const unsigned m = 0xffffffffu;
#pragma unroll
    for (int o = 16; o; o >>= 1) {
        c0 += __shfl_down_sync(m, c0, o);
        c1 += __shfl_down_sync(m, c1, o);
    }
    __shared__ float r0[4], r1[4];
    if ((tid & 31) == 0) { r0[tid >> 5] = c0; r1[tid >> 5] = c1; }
    __syncthreads();
    if (tid == 0) {
        int n = b >> 6, t = b & 63;
        out[n * 128 + t]      = (r0[0] + r0[1]) + (r0[2] + r0[3]);
        out[n * 128 + 64 + t] = (r1[0] + r1[1]) + (r1[2] + r1[3]);
    }
}

// ---------------------------------------------------------------------------
extern "C" void kernel_launch(void* const* d_in, const int* in_sizes, int n_in,
                              void* d_out, int out_size) {
    const float *inp = nullptr, *w0 = nullptr, *w1 = nullptr, *wl = nullptr;
    for (int i = 0; i < n_in; ++i) {
        switch (in_sizes[i]) {
            case 67108864: inp = (const float*)d_in[i]; break;  // (8,2,256,256,64)
            case 392:      w0  = (const float*)d_in[i]; break;  // (4,2,7,7)
            case 1568:     w1  = (const float*)d_in[i]; break;  // (8,4,7,7)
            case 256:      wl  = (const float*)d_in[i]; break;  // (2,128)
        }
    }
    // Fallback to positional order if sizes were ambiguous
    if (!inp) inp = (const float*)d_in[0];
    if (!w0)  w0  = (const float*)d_in[1];
    if (!w1)  w1  = (const float*)d_in[2];
    if (!wl)  wl  = (const float*)d_in[3];

    k_pool <<<dim3(64, 2, 8), 256>>>(inp);
    k_conv1<<<dim3(16, 8),    256>>>(w0);
    k_conv2<<<dim3(4, 8, 8),   64>>>(w1);
    k_fc   <<<512,            128>>>(wl, (float*)d_out);
}

// round 2
// speedup vs baseline: 1.6513x; 1.6513x over previous
#include <cuda_runtime.h>

// ---------------------------------------------------------------------------
// Scratch (device globals — no dynamic allocation allowed)
// ---------------------------------------------------------------------------
__device__ float g_p0[8 * 64 * 2 * 64 * 64];   // pooled input   (n,t,2,64,64)  16 MB
__device__ float g_h1[8 * 64 * 4 * 64 * 64];   // conv1 out      (n,t,4,64,64)  33.5 MB
__device__ float g_p1[8 * 64 * 4 * 16 * 16];   // pooled spikes1 (n,t,4,16,16)   2 MB
__device__ float g_h2[8 * 64 * 8 * 16 * 16];   // conv2 out      (n,t,8,16,16)   4 MB
__device__ float g_p2[8 * 64 * 128];           // features       (n,t,128)     256 KB

// ---- f32x2 packed helpers --------------------------------------------------
__device__ __forceinline__ unsigned long long pack2(float a, float b) {
    unsigned long long r;
    asm("mov.b64 %0, {%1, %2};" : "=l"(r) : "r"(__float_as_uint(a)), "r"(__float_as_uint(b)));
    return r;
}
__device__ __forceinline__ unsigned long long fma2(unsigned long long a,
                                                   unsigned long long b,
                                                   unsigned long long c) {
    unsigned long long d;
    asm("fma.rn.f32x2 %0, %1, %2, %3;" : "=l"(d) : "l"(a), "l"(b), "l"(c));
    return d;
}
__device__ __forceinline__ float2 unpack2(unsigned long long v) {
    unsigned lo, hi;
    asm("mov.b64 {%0, %1}, %2;" : "=r"(lo), "=r"(hi) : "l"(v));
    return make_float2(__uint_as_float(lo), __uint_as_float(hi));
}

// ---------------------------------------------------------------------------
// K1: avgpool4 of inp (8,2,256,256,64) -> g_p0 (n,t,2,64,64). Coalesced reads
// (t contiguous), padded-smem transpose, coalesced writes.
// ---------------------------------------------------------------------------
__global__ __launch_bounds__(256) void k_pool(const float* __restrict__ inp) {
    int Y = blockIdx.x, c = blockIdx.y, n = blockIdx.z;
    __shared__ float sm[64 * 65];
    int tid = threadIdx.x;
    int t = tid & 63, Xi = tid >> 6;
    const float* base = inp + (((n * 2 + c) * 256 + 4 * Y) * 256) * 64;
#pragma unroll
    for (int it = 0; it < 16; ++it) {
        int X = Xi + it * 4;
        float acc = 0.f;
#pragma unroll
        for (int dy = 0; dy < 4; ++dy)
#pragma unroll
            for (int dx = 0; dx < 4; ++dx)
                acc += base[(dy * 256 + 4 * X + dx) * 64 + t];
        sm[X * 65 + t] = acc * 0.0625f;
    }
    __syncthreads();
    float* ob = g_p0 + n * 524288 + c * 4096 + Y * 64;
#pragma unroll
    for (int it = 0; it < 16; ++it) {
        int idx = it * 256 + tid;
        int tw = idx >> 6, Xw = idx & 63;
        ob[tw * 8192 + Xw] = sm[Xw * 65 + tw];
    }
}

// ---------------------------------------------------------------------------
// K2: conv7 (2->4ch, pad 3) on 64x64, NO IAF — parallel over (tile, t-pair, n).
// Thread = 1 pixel x 4 couts x 2 t-steps packed into f32x2 accumulators.
// ---------------------------------------------------------------------------
__global__ __launch_bounds__(256) void k_conv1mm(const float* __restrict__ w0) {
    int tile = blockIdx.x, tp = blockIdx.y, n = blockIdx.z;
    int t0 = tp * 2;
    int tid = threadIdx.x;
    int y = tid >> 6, x = tid & 63;

    __shared__ float si[2][1400];          // [t][cin 2][row 10][col 70]
    __shared__ ulonglong2 swq[98][2];      // per tap: {w0w0,w1w1},{w2w2,w3w3}

    if (tid < 98) {
        int cin = tid / 49, j = tid - cin * 49;
        float wa = w0[(0 * 2 + cin) * 49 + j];
        float wb = w0[(1 * 2 + cin) * 49 + j];
        float wc = w0[(2 * 2 + cin) * 49 + j];
        float wd = w0[(3 * 2 + cin) * 49 + j];
        swq[tid][0] = make_ulonglong2(pack2(wa, wa), pack2(wb, wb));
        swq[tid][1] = make_ulonglong2(pack2(wc, wc), pack2(wd, wd));
    }

    int Y0 = tile * 4;
    const float* pb = g_p0 + n * 524288;
#pragma unroll
    for (int tt = 0; tt < 2; ++tt) {
        const float* pt = pb + (t0 + tt) * 8192;
        for (int e = tid; e < 1400; e += 256) {
            int cin = e / 700, rem = e - cin * 700;
            int r = rem / 70, col = rem - r * 70;
            int gy = Y0 - 3 + r, gx = col - 3;
            float val = 0.f;
            if ((unsigned)gy < 64u && (unsigned)gx < 64u)
                val = pt[cin * 4096 + gy * 64 + gx];
            si[tt][e] = val;
        }
    }
    __syncthreads();

    unsigned long long a0 = 0ull, a1 = 0ull, a2 = 0ull, a3 = 0ull;
#pragma unroll
    for (int cin = 0; cin < 2; ++cin)
#pragma unroll
        for (int dy = 0; dy < 7; ++dy)
#pragma unroll
            for (int dx = 0; dx < 7; ++dx) {
                int idx = cin * 700 + (y + dy) * 70 + (x + dx);
                unsigned long long v = pack2(si[0][idx], si[1][idx]);
                ulonglong2 wA = swq[cin * 49 + dy * 7 + dx][0];
                ulonglong2 wB = swq[cin * 49 + dy * 7 + dx][1];
                a0 = fma2(v, wA.x, a0);
                a1 = fma2(v, wA.y, a1);
                a2 = fma2(v, wB.x, a2);
                a3 = fma2(v, wB.y, a3);
            }

    float2 f0 = unpack2(a0), f1 = unpack2(a1), f2 = unpack2(a2), f3 = unpack2(a3);
    int gy = Y0 + y;
    float* hb = g_h1 + ((long long)(n * 64 + t0) * 4) * 4096 + gy * 64 + x;
    hb[0]             = f0.x;  hb[4096]          = f1.x;
    hb[2 * 4096]      = f2.x;  hb[3 * 4096]      = f3.x;
    hb += 4 * 4096;   // t0+1
    hb[0]             = f0.y;  hb[4096]          = f1.y;
    hb[2 * 4096]      = f2.y;  hb[3 * 4096]      = f3.y;
}

// ---------------------------------------------------------------------------
// K3: IAF scan over t for layer 1 + fused avgpool4 -> g_p1 (n,t,4,16,16).
// One thread per chain; pool groups of 16 lanes reduced purely with shuffles
// (no __syncthreads in the t loop). Prefetch next t's load.
// ---------------------------------------------------------------------------
__global__ __launch_bounds__(256) void k_iaf1() {
    int Yp = blockIdx.x, co = blockIdx.y, n = blockIdx.z;
    int tid = threadIdx.x;
    int Xp = tid >> 4;                 // pool group (0..15)
    int s  = tid & 15;
    int y = Yp * 4 + (s >> 2);
    int x = Xp * 4 + (s & 3);

    const float* hb = g_h1 + (long long)(n * 64) * 4 * 4096 + co * 4096 + y * 64 + x;
    float* ob = g_p1 + (n * 64) * 1024 + co * 256 + Yp * 16 + Xp;
    const unsigned m = 0xffffffffu;

    float v = 0.f;
    float nxt = hb[0];
    for (int t = 0; t < 64; ++t) {
        float hv = nxt;
        if (t < 63) nxt = hb[(t + 1) * 16384];
        v += hv;
        float sp = (v >= 1.f) ? 1.f : 0.f;
        v -= sp;
        sp += __shfl_down_sync(m, sp, 8);
        sp += __shfl_down_sync(m, sp, 4);
        sp += __shfl_down_sync(m, sp, 2);
        sp += __shfl_down_sync(m, sp, 1);
        if (s == 0) ob[t * 1024] = sp * 0.0625f;
    }
}

// ---------------------------------------------------------------------------
// K4: conv7 (4->8ch, pad 3) on 16x16, parallel over (t-pair, n).
// Block = 256 threads = full 16x16 image; 8 couts x 2 t per thread (f32x2).
// ---------------------------------------------------------------------------
__global__ __launch_bounds__(256) void k_conv2mm(const float* __restrict__ w1) {
    int tp = blockIdx.x, n = blockIdx.y;
    int t0 = tp * 2;
    int tid = threadIdx.x;
    int y = tid >> 4, x = tid & 15;

    __shared__ float si[2][1936];          // [t][cin 4][row 22][col 22]
    __shared__ ulonglong2 swq[196][4];     // per tap: 8 couts pre-split pairs

    if (tid < 196) {
        int cin = tid / 49, j = tid - cin * 49;
#pragma unroll
        for (int p = 0; p < 4; ++p) {
            float wa = w1[((2 * p + 0) * 4 + cin) * 49 + j];
            float wb = w1[((2 * p + 1) * 4 + cin) * 49 + j];
            swq[tid][p] = make_ulonglong2(pack2(wa, wa), pack2(wb, wb));
        }
    }

    const float* pb = g_p1 + n * 65536;
#pragma unroll
    for (int tt = 0; tt < 2; ++tt) {
        const float* pt = pb + (t0 + tt) * 1024;
        for (int e = tid; e < 1936; e += 256) {
            int cin = e / 484, rem = e - cin * 484;
            int r = rem / 22, col = rem - r * 22;
            int gy = r - 3, gx = col - 3;
            float val = 0.f;
            if ((unsigned)gy < 16u && (unsigned)gx < 16u)
                val = pt[cin * 256 + gy * 16 + gx];
            si[tt][e] = val;
        }
    }
    __syncthreads();

    unsigned long long a[8];
#pragma unroll
    for (int i = 0; i < 8; ++i) a[i] = 0ull;

#pragma unroll 1
    for (int cin = 0; cin < 4; ++cin)
#pragma unroll
        for (int dy = 0; dy < 7; ++dy)
#pragma unroll
            for (int dx = 0; dx < 7; ++dx) {
                int idx = cin * 484 + (y + dy) * 22 + (x + dx);
                unsigned long long v = pack2(si[0][idx], si[1][idx]);
                int k = cin * 49 + dy * 7 + dx;
#pragma unroll
                for (int p = 0; p < 4; ++p) {
                    ulonglong2 w = swq[k][p];
                    a[2 * p]     = fma2(v, w.x, a[2 * p]);
                    a[2 * p + 1] = fma2(v, w.y, a[2 * p + 1]);
                }
            }

    float* hb = g_h2 + (long long)(n * 64 + t0) * 8 * 256 + y * 16 + x;
#pragma unroll
    for (int co = 0; co < 8; ++co) {
        float2 f = unpack2(a[co]);
        hb[co * 256]            = f.x;
        hb[co * 256 + 8 * 256]  = f.y;   // t0+1
    }
}

// ---------------------------------------------------------------------------
// K5: IAF scan layer 2 + avgpool4 -> g_p2 features (n,t,128).
// ---------------------------------------------------------------------------
__global__ __launch_bounds__(256) void k_iaf2() {
    int co = blockIdx.x, n = blockIdx.y;
    int tid = threadIdx.x;
    int g = tid >> 4;                      // pooled idx = Py*4+Px (0..15)
    int s = tid & 15;
    int y = (g >> 2) * 4 + (s >> 2);
    int x = (g & 3) * 4 + (s & 3);

    const float* hb = g_h2 + (long long)(n * 64) * 8 * 256 + co * 256 + y * 16 + x;
    float* ob = g_p2 + (n * 64) * 128 + co * 16 + g;
    const unsigned m = 0xffffffffu;

    float v = 0.f;
    float nxt = hb[0];
    for (int t = 0; t < 64; ++t) {
        float hv = nxt;
        if (t < 63) nxt = hb[(t + 1) * 2048];
        v += hv;
        float sp = (v >= 1.f) ? 1.f : 0.f;
        v -= sp;
        sp += __shfl_down_sync(m, sp, 8);
        sp += __shfl_down_sync(m, sp, 4);
        sp += __shfl_down_sync(m, sp, 2);
        sp += __shfl_down_sync(m, sp, 1);
        if (s == 0) ob[t * 128] = sp * 0.0625f;
    }
}

// ---------------------------------------------------------------------------
// K6: out[n][cls][t] = sum_f feat[n][t][f] * wl[cls][f]   -> (8,2,64)
// ---------------------------------------------------------------------------
__global__ __launch_bounds__(128) void k_fc(const float* __restrict__ wl,
                                            float* __restrict__ out) {
    int b = blockIdx.x;          // n*64 + t
    int tid = threadIdx.x;
    float v = g_p2[b * 128 + tid];
    float c0 = v * wl[tid];
    float c1 = v * wl[128 + tid];
    const unsigned m = 0xffffffffu;
#pragma unroll
    for (int o = 16; o; o >>= 1) {
        c0 += __shfl_down_sync(m, c0, o);
        c1 += __shfl_down_sync(m, c1, o);
    }
    __shared__ float r0[4], r1[4];
    if ((tid & 31) == 0) { r0[tid >> 5] = c0; r1[tid >> 5] = c1; }
    __syncthreads();
    if (tid == 0) {
        int n = b >> 6, t = b & 63;
        out[n * 128 + t]      = (r0[0] + r0[1]) + (r0[2] + r0[3]);
        out[n * 128 + 64 + t] = (r1[0] + r1[1]) + (r1[2] + r1[3]);
    }
}

// ---------------------------------------------------------------------------
extern "C" void kernel_launch(void* const* d_in, const int* in_sizes, int n_in,
                              void* d_out, int out_size) {
    const float *inp = nullptr, *w0 = nullptr, *w1 = nullptr, *wl = nullptr;
    for (int i = 0; i < n_in; ++i) {
        switch (in_sizes[i]) {
            case 67108864: inp = (const float*)d_in[i]; break;  // (8,2,256,256,64)
            case 392:      w0  = (const float*)d_in[i]; break;  // (4,2,7,7)
            case 1568:     w1  = (const float*)d_in[i]; break;  // (8,4,7,7)
            case 256:      wl  = (const float*)d_in[i]; break;  // (2,128)
        }
    }
    if (!inp) inp = (const float*)d_in[0];
    if (!w0)  w0  = (const float*)d_in[1];
    if (!w1)  w1  = (const float*)d_in[2];
    if (!wl)  wl  = (const float*)d_in[3];

    k_pool   <<<dim3(64, 2, 8),  256>>>(inp);
    k_conv1mm<<<dim3(16, 32, 8), 256>>>(w0);
    k_iaf1   <<<dim3(16, 4, 8),  256>>>();
    k_conv2mm<<<dim3(32, 8),     256>>>(w1);
    k_iaf2   <<<dim3(8, 8),      256>>>();
    k_fc     <<<512,             128>>>(wl, (float*)d_out);
}

// round 3
// speedup vs baseline: 2.5733x; 1.5584x over previous
#include <cuda_runtime.h>

// ---------------------------------------------------------------------------
// Scratch (device globals — no dynamic allocation allowed)
// ---------------------------------------------------------------------------
__device__ float g_p0[8 * 64 * 2 * 64 * 64];   // pooled input   (n,t,2,64,64)  16 MB
__device__ float g_h1[8 * 64 * 4 * 64 * 64];   // conv1 out      (n,t,4,64,64)  33.5 MB
__device__ float g_p1[8 * 64 * 4 * 16 * 16];   // pooled spikes1 (n,t,4,16,16)   2 MB
__device__ float g_h2[8 * 64 * 8 * 16 * 16];   // conv2 out      (n,t,8,16,16)   4 MB
__device__ float g_p2[8 * 64 * 128];           // features       (n,t,128)     256 KB

// ---- f32x2 packed helpers --------------------------------------------------
__device__ __forceinline__ unsigned long long pack2(float a, float b) {
    unsigned long long r;
    asm("mov.b64 %0, {%1, %2};" : "=l"(r) : "r"(__float_as_uint(a)), "r"(__float_as_uint(b)));
    return r;
}
__device__ __forceinline__ unsigned long long fma2(unsigned long long a,
                                                   unsigned long long b,
                                                   unsigned long long c) {
    unsigned long long d;
    asm("fma.rn.f32x2 %0, %1, %2, %3;" : "=l"(d) : "l"(a), "l"(b), "l"(c));
    return d;
}
__device__ __forceinline__ float2 unpack2(unsigned long long v) {
    unsigned lo, hi;
    asm("mov.b64 {%0, %1}, %2;" : "=r"(lo), "=r"(hi) : "l"(v));
    return make_float2(__uint_as_float(lo), __uint_as_float(hi));
}

// ---------------------------------------------------------------------------
// K1: avgpool4 of inp (8,2,256,256,64) -> g_p0 (n,t,2,64,64). Coalesced reads
// (t contiguous), padded-smem transpose, coalesced writes. HBM-bound.
// ---------------------------------------------------------------------------
__global__ __launch_bounds__(256) void k_pool(const float* __restrict__ inp) {
    int Y = blockIdx.x, c = blockIdx.y, n = blockIdx.z;
    __shared__ float sm[64 * 65];
    int tid = threadIdx.x;
    int t = tid & 63, Xi = tid >> 6;
    const float* base = inp + (((n * 2 + c) * 256 + 4 * Y) * 256) * 64;
#pragma unroll
    for (int it = 0; it < 16; ++it) {
        int X = Xi + it * 4;
        float acc = 0.f;
#pragma unroll
        for (int dy = 0; dy < 4; ++dy)
#pragma unroll
            for (int dx = 0; dx < 4; ++dx)
                acc += base[(dy * 256 + 4 * X + dx) * 64 + t];
        sm[X * 65 + t] = acc * 0.0625f;
    }
    __syncthreads();
    float* ob = g_p0 + n * 524288 + c * 4096 + Y * 64;
#pragma unroll
    for (int it = 0; it < 16; ++it) {
        int idx = it * 256 + tid;
        int tw = idx >> 6, Xw = idx & 63;
        ob[tw * 8192 + Xw] = sm[Xw * 65 + tw];
    }
}

// ---------------------------------------------------------------------------
// K2: conv7 (2->4ch) on 64x64, register-blocked: thread = 4 y-rows x 4 couts
// x 2 t (f32x2). smem holds t-pair interleaved float2 tile -> LDS.64 loads.
// Grid: (ytile16 4, tpair 32, n 8) = 1024 blocks x 256 threads.
// ---------------------------------------------------------------------------
__global__ __launch_bounds__(256, 2) void k_conv1mm(const float* __restrict__ w0) {
    int tile = blockIdx.x, tp = blockIdx.y, n = blockIdx.z;
    int t0 = tp * 2;
    int tid = threadIdx.x;
    int x = tid & 63, q = tid >> 6;          // q: y-quad within 16-row tile

    __shared__ float2 si[3080];              // [cin 2][row 22][col 70], (t0,t1)
    __shared__ ulonglong2 swq[98][2];        // per tap: {(w0,w0),(w1,w1)},{(w2,w2),(w3,w3)}

    if (tid < 98) {
        int cin = tid / 49, j = tid - cin * 49;
        float wa = w0[(0 * 2 + cin) * 49 + j];
        float wb = w0[(1 * 2 + cin) * 49 + j];
        float wc = w0[(2 * 2 + cin) * 49 + j];
        float wd = w0[(3 * 2 + cin) * 49 + j];
        swq[tid][0] = make_ulonglong2(pack2(wa, wa), pack2(wb, wb));
        swq[tid][1] = make_ulonglong2(pack2(wc, wc), pack2(wd, wd));
    }

    int Y0 = tile * 16;
    const float* pt0 = g_p0 + n * 524288 + t0 * 8192;
    const float* pt1 = pt0 + 8192;
    for (int e = tid; e < 3080; e += 256) {
        int cin = e / 1540, rem = e - cin * 1540;
        int r = rem / 70, col = rem - r * 70;
        int gy = Y0 - 3 + r, gx = col - 3;
        float2 v = make_float2(0.f, 0.f);
        if ((unsigned)gy < 64u && (unsigned)gx < 64u) {
            int off = cin * 4096 + gy * 64 + gx;
            v.x = pt0[off];
            v.y = pt1[off];
        }
        si[e] = v;
    }
    __syncthreads();

    unsigned long long a[4][4];              // [row r][cout]
#pragma unroll
    for (int r = 0; r < 4; ++r)
#pragma unroll
        for (int co = 0; co < 4; ++co) a[r][co] = 0ull;

    const unsigned long long* sb = reinterpret_cast<const unsigned long long*>(si);
#pragma unroll 1
    for (int dx = 0; dx < 7; ++dx) {
#pragma unroll
        for (int cin = 0; cin < 2; ++cin) {
            const unsigned long long* colp = sb + cin * 1540 + (q * 4) * 70 + (x + dx);
            unsigned long long v[10];
#pragma unroll
            for (int r = 0; r < 10; ++r) v[r] = colp[r * 70];
#pragma unroll
            for (int dy = 0; dy < 7; ++dy) {
                ulonglong2 wA = swq[cin * 49 + dy * 7 + dx][0];
                ulonglong2 wB = swq[cin * 49 + dy * 7 + dx][1];
#pragma unroll
                for (int r = 0; r < 4; ++r) {
                    a[r][0] = fma2(v[dy + r], wA.x, a[r][0]);
                    a[r][1] = fma2(v[dy + r], wA.y, a[r][1]);
                    a[r][2] = fma2(v[dy + r], wB.x, a[r][2]);
                    a[r][3] = fma2(v[dy + r], wB.y, a[r][3]);
                }
            }
        }
    }

    long long base = ((long long)(n * 64 + t0) * 4) * 4096;
    int ybase = Y0 + q * 4;
#pragma unroll
    for (int r = 0; r < 4; ++r)
#pragma unroll
        for (int co = 0; co < 4; ++co) {
            float2 f = unpack2(a[r][co]);
            g_h1[base + co * 4096 + (ybase + r) * 64 + x]         = f.x;
            g_h1[base + 16384 + co * 4096 + (ybase + r) * 64 + x] = f.y;
        }
}

// ---------------------------------------------------------------------------
// K3: IAF scan layer 1 + fused avgpool4 -> g_p1. Warp covers 4 rows x 8
// consecutive x (full 32B sectors). Pure shfl reduction, 1-deep prefetch.
// Grid (Yp 16, co 4, n 8) x 256 threads = all 131072 chains.
// ---------------------------------------------------------------------------
__global__ __launch_bounds__(256) void k_iaf1() {
    int Yp = blockIdx.x, co = blockIdx.y, n = blockIdx.z;
    int tid = threadIdx.x;
    int w = tid >> 5, lane = tid & 31;
    int yin = lane >> 3, x8 = lane & 7;
    int x = w * 8 + x8;
    int y = Yp * 4 + yin;

    const float* hb = g_h1 + (long long)(n * 64) * 16384 + co * 4096 + y * 64 + x;
    float* ob = g_p1 + (n * 64) * 1024 + co * 256 + Yp * 16 + (x >> 2);
    const unsigned m = 0xffffffffu;

    float v = 0.f;
    float nxt = hb[0];
    for (int t = 0; t < 64; ++t) {
        float hv = nxt;
        if (t < 63) nxt = hb[(t + 1) * 16384];
        v += hv;
        float sp = (v >= 1.f) ? 1.f : 0.f;
        v -= sp;
        sp += __shfl_down_sync(m, sp, 1);
        sp += __shfl_down_sync(m, sp, 2);
        sp += __shfl_down_sync(m, sp, 8);
        sp += __shfl_down_sync(m, sp, 16);
        if (yin == 0 && (x8 & 3) == 0) ob[t * 1024] = sp * 0.0625f;
    }
}

// ---------------------------------------------------------------------------
// K4: conv7 (4->8ch) on 16x16, one t per block, cout-paired f32x2.
// Grid (t 64, cohalf 2, n 8) = 1024 blocks x 256 threads (= 16x16 pixels).
// Per tap: 1 LDS.32 + 1 LDS.128 bcast + 2 FMA2.
// ---------------------------------------------------------------------------
__global__ __launch_bounds__(256) void k_conv2mm(const float* __restrict__ w1) {
    int t = blockIdx.x, h = blockIdx.y, n = blockIdx.z;
    int tid = threadIdx.x;
    int y = tid >> 4, x = tid & 15;

    __shared__ float si[1936];               // [cin 4][22][22]
    __shared__ ulonglong2 swp[196];          // per tap: (w4h,w4h+1),(w4h+2,w4h+3)

    if (tid < 196) {
        int cin = tid / 49, j = tid - cin * 49;
        float wa = w1[((h * 4 + 0) * 4 + cin) * 49 + j];
        float wb = w1[((h * 4 + 1) * 4 + cin) * 49 + j];
        float wc = w1[((h * 4 + 2) * 4 + cin) * 49 + j];
        float wd = w1[((h * 4 + 3) * 4 + cin) * 49 + j];
        swp[tid] = make_ulonglong2(pack2(wa, wb), pack2(wc, wd));
    }

    const float* pt = g_p1 + n * 65536 + t * 1024;
    for (int e = tid; e < 1936; e += 256) {
        int cin = e / 484, rem = e - cin * 484;
        int r = rem / 22, col = rem - r * 22;
        int gy = r - 3, gx = col - 3;
        float val = 0.f;
        if ((unsigned)gy < 16u && (unsigned)gx < 16u)
            val = pt[cin * 256 + gy * 16 + gx];
        si[e] = val;
    }
    __syncthreads();

    unsigned long long a01 = 0ull, a23 = 0ull;
#pragma unroll 1
    for (int cin = 0; cin < 4; ++cin)
#pragma unroll
        for (int dy = 0; dy < 7; ++dy)
#pragma unroll
            for (int dx = 0; dx < 7; ++dx) {
                float vv = si[cin * 484 + (y + dy) * 22 + (x + dx)];
                unsigned long long v2 = pack2(vv, vv);
                ulonglong2 wq = swp[cin * 49 + dy * 7 + dx];
                a01 = fma2(v2, wq.x, a01);
                a23 = fma2(v2, wq.y, a23);
            }

    float2 f01 = unpack2(a01), f23 = unpack2(a23);
    float* hb = g_h2 + ((long long)(n * 64 + t) * 8 + h * 4) * 256 + y * 16 + x;
    hb[0]   = f01.x;
    hb[256] = f01.y;
    hb[512] = f23.x;
    hb[768] = f23.y;
}

// ---------------------------------------------------------------------------
// K5: IAF scan layer 2 + avgpool4 -> g_p2 (n,t,128). Warp covers 4 rows x 8 x.
// Grid (co 8, n 8) x 256 threads = all 16384 chains.
// ---------------------------------------------------------------------------
__global__ __launch_bounds__(256) void k_iaf2() {
    int co = blockIdx.x, n = blockIdx.y;
    int tid = threadIdx.x;
    int w = tid >> 5, lane = tid & 31;
    int yin = lane >> 3, x8 = lane & 7;
    int y = (w >> 1) * 4 + yin;
    int x = (w & 1) * 8 + x8;
    int g = (y >> 2) * 4 + (x >> 2);

    const float* hb = g_h2 + (long long)(n * 64) * 2048 + co * 256 + y * 16 + x;
    float* ob = g_p2 + (n * 64) * 128 + co * 16 + g;
    const unsigned m = 0xffffffffu;

    float v = 0.f;
    float nxt = hb[0];
    for (int t = 0; t < 64; ++t) {
        float hv = nxt;
        if (t < 63) nxt = hb[(t + 1) * 2048];
        v += hv;
        float sp = (v >= 1.f) ? 1.f : 0.f;
        v -= sp;
        sp += __shfl_down_sync(m, sp, 1);
        sp += __shfl_down_sync(m, sp, 2);
        sp += __shfl_down_sync(m, sp, 8);
        sp += __shfl_down_sync(m, sp, 16);
        if (yin == 0 && (x8 & 3) == 0) ob[t * 128] = sp * 0.0625f;
    }
}

// ---------------------------------------------------------------------------
// K6: out[n][cls][t] = sum_f feat[n][t][f] * wl[cls][f]   -> (8,2,64)
// ---------------------------------------------------------------------------
__global__ __launch_bounds__(128) void k_fc(const float* __restrict__ wl,
                                            float* __restrict__ out) {
    int b = blockIdx.x;          // n*64 + t
    int tid = threadIdx.x;
    float v = g_p2[b * 128 + tid];
    float c0 = v * wl[tid];
    float c1 = v * wl[128 + tid];
    const unsigned m = 0xffffffffu;
#pragma unroll
    for (int o = 16; o; o >>= 1) {
        c0 += __shfl_down_sync(m, c0, o);
        c1 += __shfl_down_sync(m, c1, o);
    }
    __shared__ float r0[4], r1[4];
    if ((tid & 31) == 0) { r0[tid >> 5] = c0; r1[tid >> 5] = c1; }
    __syncthreads();
    if (tid == 0) {
        int n = b >> 6, t = b & 63;
        out[n * 128 + t]      = (r0[0] + r0[1]) + (r0[2] + r0[3]);
        out[n * 128 + 64 + t] = (r1[0] + r1[1]) + (r1[2] + r1[3]);
    }
}

// ---------------------------------------------------------------------------
extern "C" void kernel_launch(void* const* d_in, const int* in_sizes, int n_in,
                              void* d_out, int out_size) {
    const float *inp = nullptr, *w0 = nullptr, *w1 = nullptr, *wl = nullptr;
    for (int i = 0; i < n_in; ++i) {
        switch (in_sizes[i]) {
            case 67108864: inp = (const float*)d_in[i]; break;  // (8,2,256,256,64)
            case 392:      w0  = (const float*)d_in[i]; break;  // (4,2,7,7)
            case 1568:     w1  = (const float*)d_in[i]; break;  // (8,4,7,7)
            case 256:      wl  = (const float*)d_in[i]; break;  // (2,128)
        }
    }
    if (!inp) inp = (const float*)d_in[0];
    if (!w0)  w0  = (const float*)d_in[1];
    if (!w1)  w1  = (const float*)d_in[2];
    if (!wl)  wl  = (const float*)d_in[3];

    k_pool   <<<dim3(64, 2, 8),  256>>>(inp);
    k_conv1mm<<<dim3(4, 32, 8),  256>>>(w0);
    k_iaf1   <<<dim3(16, 4, 8),  256>>>();
    k_conv2mm<<<dim3(64, 2, 8),  256>>>(w1);
    k_iaf2   <<<dim3(8, 8),      256>>>();
    k_fc     <<<512,             128>>>(wl, (float*)d_out);
}

// round 5
// speedup vs baseline: 2.9204x; 1.1349x over previous
#include <cuda_runtime.h>

// ---------------------------------------------------------------------------
// Scratch (device globals — no dynamic allocation allowed)
// ---------------------------------------------------------------------------
__device__ float g_p0[8 * 64 * 2 * 64 * 64];   // pooled input   (n,t,2,64,64)  16 MB
__device__ float g_h1[8 * 64 * 4 * 64 * 64];   // conv1 out      (n,t,4,64,64)  33.5 MB
__device__ float g_p1[8 * 64 * 4 * 16 * 16];   // pooled spikes1 (n,t,4,16,16)   2 MB
__device__ float g_h2[8 * 64 * 8 * 16 * 16];   // conv2 out      (n,t,8,16,16)   4 MB
__device__ float g_p2[8 * 64 * 128];           // features       (n,t,128)     256 KB

// ---- f32x2 packed helpers --------------------------------------------------
__device__ __forceinline__ unsigned long long pack2(float a, float b) {
    unsigned long long r;
    asm("mov.b64 %0, {%1, %2};" : "=l"(r) : "r"(__float_as_uint(a)), "r"(__float_as_uint(b)));
    return r;
}
__device__ __forceinline__ unsigned long long fma2(unsigned long long a,
                                                   unsigned long long b,
                                                   unsigned long long c) {
    unsigned long long d;
    asm("fma.rn.f32x2 %0, %1, %2, %3;" : "=l"(d) : "l"(a), "l"(b), "l"(c));
    return d;
}
__device__ __forceinline__ float2 unpack2(unsigned long long v) {
    unsigned lo, hi;
    asm("mov.b64 {%0, %1}, %2;" : "=r"(lo), "=r"(hi) : "l"(v));
    return make_float2(__uint_as_float(lo), __uint_as_float(hi));
}

// ---------------------------------------------------------------------------
// K1: avgpool4 of inp (8,2,256,256,64) -> g_p0 (n,t,2,64,64). float4 loads
// over t (LDG.128, 4x MLP bytes), padded-smem transpose, coalesced writes.
// ---------------------------------------------------------------------------
__global__ __launch_bounds__(256) void k_pool(const float* __restrict__ inp) {
    int Y = blockIdx.x, c = blockIdx.y, n = blockIdx.z;
    __shared__ float sm[64 * 65];
    int tid = threadIdx.x;
    int t4 = tid & 15, Xi = tid >> 4;
    const float4* base =
        reinterpret_cast<const float4*>(inp + (((long long)(n * 2 + c) * 256 + 4 * Y) * 256) * 64) + t4;
#pragma unroll
    for (int it = 0; it < 4; ++it) {
        int X = Xi + 16 * it;
        float4 acc = make_float4(0.f, 0.f, 0.f, 0.f);
#pragma unroll
        for (int dy = 0; dy < 4; ++dy)
#pragma unroll
            for (int dx = 0; dx < 4; ++dx) {
                float4 v = base[(dy * 256 + 4 * X + dx) * 16];
                acc.x += v.x; acc.y += v.y; acc.z += v.z; acc.w += v.w;
            }
        sm[X * 65 + 4 * t4 + 0] = acc.x * 0.0625f;
        sm[X * 65 + 4 * t4 + 1] = acc.y * 0.0625f;
        sm[X * 65 + 4 * t4 + 2] = acc.z * 0.0625f;
        sm[X * 65 + 4 * t4 + 3] = acc.w * 0.0625f;
    }
    __syncthreads();
    float* ob = g_p0 + n * 524288 + c * 4096 + Y * 64;
#pragma unroll
    for (int it = 0; it < 16; ++it) {
        int idx = it * 256 + tid;
        int tw = idx >> 6, Xw = idx & 63;
        ob[tw * 8192 + Xw] = sm[Xw * 65 + tw];
    }
}

// ---------------------------------------------------------------------------
// K2: conv7 (2->4ch) on 64x64, register-blocked: thread = 4 y-rows x 4 couts
// x 2 t (f32x2). smem holds t-pair interleaved float2 tile -> LDS.64 loads.
// Grid: (ytile16 4, tpair 32, n 8) = 1024 blocks x 256 threads.
// ---------------------------------------------------------------------------
__global__ __launch_bounds__(256, 2) void k_conv1mm(const float* __restrict__ w0) {
    int tile = blockIdx.x, tp = blockIdx.y, n = blockIdx.z;
    int t0 = tp * 2;
    int tid = threadIdx.x;
    int x = tid & 63, q = tid >> 6;          // q: y-quad within 16-row tile

    __shared__ float2 si[3080];              // [cin 2][row 22][col 70], (t0,t1)
    __shared__ ulonglong2 swq[98][2];        // per tap: {(w0,w0),(w1,w1)},{(w2,w2),(w3,w3)}

    if (tid < 98) {
        int cin = tid / 49, j = tid - cin * 49;
        float wa = w0[(0 * 2 + cin) * 49 + j];
        float wb = w0[(1 * 2 + cin) * 49 + j];
        float wc = w0[(2 * 2 + cin) * 49 + j];
        float wd = w0[(3 * 2 + cin) * 49 + j];
        swq[tid][0] = make_ulonglong2(pack2(wa, wa), pack2(wb, wb));
        swq[tid][1] = make_ulonglong2(pack2(wc, wc), pack2(wd, wd));
    }

    int Y0 = tile * 16;
    const float* pt0 = g_p0 + n * 524288 + t0 * 8192;
    const float* pt1 = pt0 + 8192;
    for (int e = tid; e < 3080; e += 256) {
        int cin = e / 1540, rem = e - cin * 1540;
        int r = rem / 70, col = rem - r * 70;
        int gy = Y0 - 3 + r, gx = col - 3;
        float2 v = make_float2(0.f, 0.f);
        if ((unsigned)gy < 64u && (unsigned)gx < 64u) {
            int off = cin * 4096 + gy * 64 + gx;
            v.x = pt0[off];
            v.y = pt1[off];
        }
        si[e] = v;
    }
    __syncthreads();

    unsigned long long a[4][4];              // [row r][cout]
#pragma unroll
    for (int r = 0; r < 4; ++r)
#pragma unroll
        for (int co = 0; co < 4; ++co) a[r][co] = 0ull;

    const unsigned long long* sb = reinterpret_cast<const unsigned long long*>(si);
#pragma unroll 1
    for (int dx = 0; dx < 7; ++dx) {
#pragma unroll
        for (int cin = 0; cin < 2; ++cin) {
            const unsigned long long* colp = sb + cin * 1540 + (q * 4) * 70 + (x + dx);
            unsigned long long v[10];
#pragma unroll
            for (int r = 0; r < 10; ++r) v[r] = colp[r * 70];
#pragma unroll
            for (int dy = 0; dy < 7; ++dy) {
                ulonglong2 wA = swq[cin * 49 + dy * 7 + dx][0];
                ulonglong2 wB = swq[cin * 49 + dy * 7 + dx][1];
#pragma unroll
                for (int r = 0; r < 4; ++r) {
                    a[r][0] = fma2(v[dy + r], wA.x, a[r][0]);
                    a[r][1] = fma2(v[dy + r], wA.y, a[r][1]);
                    a[r][2] = fma2(v[dy + r], wB.x, a[r][2]);
                    a[r][3] = fma2(v[dy + r], wB.y, a[r][3]);
                }
            }
        }
    }

    long long base = ((long long)(n * 64 + t0) * 4) * 4096;
    int ybase = Y0 + q * 4;
#pragma unroll
    for (int r = 0; r < 4; ++r)
#pragma unroll
        for (int co = 0; co < 4; ++co) {
            float2 f = unpack2(a[r][co]);
            g_h1[base + co * 4096 + (ybase + r) * 64 + x]         = f.x;
            g_h1[base + 16384 + co * 4096 + (ybase + r) * 64 + x] = f.y;
        }
}

// ---------------------------------------------------------------------------
// K3: IAF scan layer 1 + fused avgpool4 -> g_p1. Warp covers 4 rows x 8
// consecutive x (full 32B sectors). Pure shfl reduction, 1-deep prefetch.
// ---------------------------------------------------------------------------
__global__ __launch_bounds__(256) void k_iaf1() {
    int Yp = blockIdx.x, co = blockIdx.y, n = blockIdx.z;
    int tid = threadIdx.x;
    int w = tid >> 5, lane = tid & 31;
    int yin = lane >> 3, x8 = lane & 7;
    int x = w * 8 + x8;
    int y = Yp * 4 + yin;

    const float* hb = g_h1 + (long long)(n * 64) * 16384 + co * 4096 + y * 64 + x;
    float* ob = g_p1 + (n * 64) * 1024 + co * 256 + Yp * 16 + (x >> 2);
    const unsigned m = 0xffffffffu;

    float v = 0.f;
    float nxt = hb[0];
    for (int t = 0; t < 64; ++t) {
        float hv = nxt;
        if (t < 63) nxt = hb[(t + 1) * 16384];
        v += hv;
        float sp = (v >= 1.f) ? 1.f : 0.f;
        v -= sp;
        sp += __shfl_down_sync(m, sp, 1);
        sp += __shfl_down_sync(m, sp, 2);
        sp += __shfl_down_sync(m, sp, 8);
        sp += __shfl_down_sync(m, sp, 16);
        if (yin == 0 && (x8 & 3) == 0) ob[t * 1024] = sp * 0.0625f;
    }
}

// ---------------------------------------------------------------------------
// K4: conv7 (4->8ch) on 16x16, register-blocked: thread = 4 y-rows x 8 couts
// (4 f32x2 cout-pairs). 64-thread group per t, 2 t per 128-thread block.
// Grid (tp 32, n 8) = 256 blocks. Per (cin,dx): 10 LDS.32 + 14 bcast LDS.128
// feed 112 FMA2.
// ---------------------------------------------------------------------------
__global__ __launch_bounds__(128) void k_conv2mm(const float* __restrict__ w1) {
    int tp = blockIdx.x, n = blockIdx.y;
    int tid = threadIdx.x;
    int sub = tid >> 6;                     // which t of the pair
    int lt = tid & 63;
    int x = lt & 15, q = lt >> 4;           // q: y-quad (rows q*4..q*4+3)
    int t = tp * 2 + sub;

    __shared__ float si[2][1936];           // [sub][cin 4][22][22]
    __shared__ ulonglong2 swq[196][2];      // per tap: {(w0,w1),(w2,w3)},{(w4,w5),(w6,w7)}

    // FIX (R4 bug): block is 128 threads — stride the 196-entry weight load.
    for (int e = tid; e < 196; e += 128) {
        int cin = e / 49, j = e - cin * 49;
        float w[8];
#pragma unroll
        for (int co = 0; co < 8; ++co) w[co] = w1[(co * 4 + cin) * 49 + j];
        swq[e][0] = make_ulonglong2(pack2(w[0], w[1]), pack2(w[2], w[3]));
        swq[e][1] = make_ulonglong2(pack2(w[4], w[5]), pack2(w[6], w[7]));
    }

    const float* pt = g_p1 + n * 65536 + t * 1024;
    for (int e = lt; e < 1936; e += 64) {
        int cin = e / 484, rem = e - cin * 484;
        int r = rem / 22, col = rem - r * 22;
        int gy = r - 3, gx = col - 3;
        float val = 0.f;
        if ((unsigned)gy < 16u && (unsigned)gx < 16u)
            val = pt[cin * 256 + gy * 16 + gx];
        si[sub][e] = val;
    }
    __syncthreads();

    unsigned long long a[4][4];             // [row r][cout-pair p]
#pragma unroll
    for (int r = 0; r < 4; ++r)
#pragma unroll
        for (int p = 0; p < 4; ++p) a[r][p] = 0ull;

#pragma unroll 1
    for (int dx = 0; dx < 7; ++dx) {
#pragma unroll
        for (int cin = 0; cin < 4; ++cin) {
            const float* colp = &si[sub][cin * 484 + (q * 4) * 22 + (x + dx)];
            unsigned long long vp[10];
#pragma unroll
            for (int r = 0; r < 10; ++r) {
                float vv = colp[r * 22];
                vp[r] = pack2(vv, vv);
            }
#pragma unroll
            for (int dy = 0; dy < 7; ++dy) {
                ulonglong2 wA = swq[cin * 49 + dy * 7 + dx][0];
                ulonglong2 wB = swq[cin * 49 + dy * 7 + dx][1];
#pragma unroll
                for (int r = 0; r < 4; ++r) {
                    a[r][0] = fma2(vp[dy + r], wA.x, a[r][0]);
                    a[r][1] = fma2(vp[dy + r], wA.y, a[r][1]);
                    a[r][2] = fma2(vp[dy + r], wB.x, a[r][2]);
                    a[r][3] = fma2(vp[dy + r], wB.y, a[r][3]);
                }
            }
        }
    }

    float* hb = g_h2 + (long long)(n * 64 + t) * 2048;
#pragma unroll
    for (int r = 0; r < 4; ++r) {
        int yo = (q * 4 + r) * 16 + x;
#pragma unroll
        for (int p = 0; p < 4; ++p) {
            float2 f = unpack2(a[r][p]);
            hb[(2 * p) * 256 + yo]     = f.x;
            hb[(2 * p + 1) * 256 + yo] = f.y;
        }
    }
}

// ---------------------------------------------------------------------------
// K5: IAF scan layer 2 + avgpool4 -> g_p2 (n,t,128). Warp covers 4 rows x 8 x.
// ---------------------------------------------------------------------------
__global__ __launch_bounds__(256) void k_iaf2() {
    int co = blockIdx.x, n = blockIdx.y;
    int tid = threadIdx.x;
    int w = tid >> 5, lane = tid & 31;
    int yin = lane >> 3, x8 = lane & 7;
    int y = (w >> 1) * 4 + yin;
    int x = (w & 1) * 8 + x8;
    int g = (y >> 2) * 4 + (x >> 2);

    const float* hb = g_h2 + (long long)(n * 64) * 2048 + co * 256 + y * 16 + x;
    float* ob = g_p2 + (n * 64) * 128 + co * 16 + g;
    const unsigned m = 0xffffffffu;

    float v = 0.f;
    float nxt = hb[0];
    for (int t = 0; t < 64; ++t) {
        float hv = nxt;
        if (t < 63) nxt = hb[(t + 1) * 2048];
        v += hv;
        float sp = (v >= 1.f) ? 1.f : 0.f;
        v -= sp;
        sp += __shfl_down_sync(m, sp, 1);
        sp += __shfl_down_sync(m, sp, 2);
        sp += __shfl_down_sync(m, sp, 8);
        sp += __shfl_down_sync(m, sp, 16);
        if (yin == 0 && (x8 & 3) == 0) ob[t * 128] = sp * 0.0625f;
    }
}

// ---------------------------------------------------------------------------
// K6: out[n][cls][t] = sum_f feat[n][t][f] * wl[cls][f]   -> (8,2,64)
// ---------------------------------------------------------------------------
__global__ __launch_bounds__(128) void k_fc(const float* __restrict__ wl,
                                            float* __restrict__ out) {
    int b = blockIdx.x;          // n*64 + t
    int tid = threadIdx.x;
    float v = g_p2[b * 128 + tid];
    float c0 = v * wl[tid];
    float c1 = v * wl[128 + tid];
    const unsigned m = 0xffffffffu;
#pragma unroll
    for (int o = 16; o; o >>= 1) {
        c0 += __shfl_down_sync(m, c0, o);
        c1 += __shfl_down_sync(m, c1, o);
    }
    __shared__ float r0[4], r1[4];
    if ((tid & 31) == 0) { r0[tid >> 5] = c0; r1[tid >> 5] = c1; }
    __syncthreads();
    if (tid == 0) {
        int n = b >> 6, t = b & 63;
        out[n * 128 + t]      = (r0[0] + r0[1]) + (r0[2] + r0[3]);
        out[n * 128 + 64 + t] = (r1[0] + r1[1]) + (r1[2] + r1[3]);
    }
}

// ---------------------------------------------------------------------------
extern "C" void kernel_launch(void* const* d_in, const int* in_sizes, int n_in,
                              void* d_out, int out_size) {
    const float *inp = nullptr, *w0 = nullptr, *w1 = nullptr, *wl = nullptr;
    for (int i = 0; i < n_in; ++i) {
        switch (in_sizes[i]) {
            case 67108864: inp = (const float*)d_in[i]; break;  // (8,2,256,256,64)
            case 392:      w0  = (const float*)d_in[i]; break;  // (4,2,7,7)
            case 1568:     w1  = (const float*)d_in[i]; break;  // (8,4,7,7)
            case 256:      wl  = (const float*)d_in[i]; break;  // (2,128)
        }
    }
    if (!inp) inp = (const float*)d_in[0];
    if (!w0)  w0  = (const float*)d_in[1];
    if (!w1)  w1  = (const float*)d_in[2];
    if (!wl)  wl  = (const float*)d_in[3];

    k_pool   <<<dim3(64, 2, 8),  256>>>(inp);
    k_conv1mm<<<dim3(4, 32, 8),  256>>>(w0);
    k_iaf1   <<<dim3(16, 4, 8),  256>>>();
    k_conv2mm<<<dim3(32, 8),     128>>>(w1);
    k_iaf2   <<<dim3(8, 8),      256>>>();
    k_fc     <<<512,             128>>>(wl, (float*)d_out);
}